// round 11
// baseline (speedup 1.0000x reference)
#include <cuda_runtime.h>
#include <math.h>
#include <stdint.h>

// Problem constants
#define Bdim   2
#define Sdim   2048
#define Edim   2048
#define Hdim   16
#define HKVdim 4
#define Ddim   128
#define KQVdim 2048
#define KVdim  512            // HKV * D — compact Q / attn-out width
#define WIN    256
#define Mrows  (Bdim * Sdim)  // 4096

// Scratch (static __device__ — no allocation allowed)
__device__ float g_q [(size_t)Mrows * KVdim];
__device__ float g_k [(size_t)Mrows * KVdim];
__device__ float g_v [(size_t)Mrows * KVdim];
__device__ float g_ao[(size_t)Mrows * KVdim];
__device__ float g_wf[(size_t)Edim  * KVdim];    // folded Wo

// ---------------------------------------------------------------------------
// 3xBF16 tensor-core GEMM (fp32-accurate): Y = X @ W^T (+bias)
// BM=128, BN=64, BK=16, 256 threads (8 warps: 4 M x 2 N), 32x32 per warp,
// 2 CTAs/SM. smem holds PACKED bf16x2 hi/lo planes (same bytes as fp32):
// split once at staging; mainloop is pure LDS.32 + mma.m16n8k16.bf16.
// acc += Alo*Bhi + Ahi*Blo + Ahi*Bhi   (dropped Alo*Blo ~ 2^-18 rel)
// ---------------------------------------------------------------------------
#define BM 128
#define BN 64
#define BK 16
#define MSTR (BM + 4)   // 132
#define NSTR (BN + 4)   // 68

// pack two floats as bf16x2: low 16 bits = e0 (even k), high = e1 (odd k)
__device__ __forceinline__ uint32_t packbf(float e0, float e1) {
    uint32_t r;
    asm("cvt.rn.bf16x2.f32 %0, %1, %2;" : "=r"(r) : "f"(e1), "f"(e0));
    return r;
}

__device__ __forceinline__ void mma_bf16(float c[4], uint32_t a0, uint32_t a1,
                                         uint32_t a2, uint32_t a3,
                                         uint32_t b0, uint32_t b1) {
    asm volatile(
        "mma.sync.aligned.m16n8k16.row.col.f32.bf16.bf16.f32 "
        "{%0,%1,%2,%3}, {%4,%5,%6,%7}, {%8,%9}, {%0,%1,%2,%3};"
        : "+f"(c[0]), "+f"(c[1]), "+f"(c[2]), "+f"(c[3])
        : "r"(a0), "r"(a1), "r"(a2), "r"(a3), "r"(b0), "r"(b1));
}

// Split float4 (4 consecutive k of one row) into hi/lo bf16x2 pairs and store.
__device__ __forceinline__ void stage4(uint32_t* hiP, uint32_t* loP,
                                       int stride, int pairbase, int row,
                                       float4 v) {
    uint32_t h01 = packbf(v.x, v.y);
    uint32_t h23 = packbf(v.z, v.w);
    float lx = v.x - __uint_as_float(h01 << 16);
    float ly = v.y - __uint_as_float(h01 & 0xffff0000u);
    float lz = v.z - __uint_as_float(h23 << 16);
    float lw = v.w - __uint_as_float(h23 & 0xffff0000u);
    hiP[(pairbase + 0) * stride + row] = h01;
    hiP[(pairbase + 1) * stride + row] = h23;
    loP[(pairbase + 0) * stride + row] = packbf(lx, ly);
    loP[(pairbase + 1) * stride + row] = packbf(lz, lw);
}

// Batched: gridDim.z selects (W, Y) pair. K fixed per launch.
__global__ void __launch_bounds__(256, 2)
gemm_3xbf16(const float* __restrict__ X,
            const float* __restrict__ W0, const float* __restrict__ W1,
            const float* __restrict__ W2,
            float* __restrict__ Y0, float* __restrict__ Y1,
            float* __restrict__ Y2,
            const float* __restrict__ bias,
            int N, int K)
{
    // [stage][kpair][row/col] packed bf16x2
    __shared__ uint32_t AsH[2][8][MSTR];
    __shared__ uint32_t AsL[2][8][MSTR];
    __shared__ uint32_t BsH[2][8][NSTR];
    __shared__ uint32_t BsL[2][8][NSTR];

    const float* W = (blockIdx.z == 0) ? W0 : (blockIdx.z == 1) ? W1 : W2;
    float*       Y = (blockIdx.z == 0) ? Y0 : (blockIdx.z == 1) ? Y1 : Y2;

    const int tid  = threadIdx.x;
    const int warp = tid >> 5;
    const int lane = tid & 31;
    const int g    = lane >> 2;        // 0..7
    const int tg   = lane & 3;         // 0..3
    const int wm   = warp & 3;         // 0..3: 32 M-rows each
    const int wn   = warp >> 2;        // 0..1: 32 N-cols each
    const int bm   = blockIdx.y * BM;
    const int bn   = blockIdx.x * BN;

    const int ldrow = tid >> 2;        // 0..63
    const int ldkv  = tid & 3;         // float4 slot within BK=16

    float acc[2][4][4];
    #pragma unroll
    for (int i = 0; i < 2; i++)
        #pragma unroll
        for (int j = 0; j < 4; j++)
            #pragma unroll
            for (int c = 0; c < 4; c++) acc[i][j][c] = 0.0f;

    // bf16x2 fragment double-buffers (hi & lo planes)
    uint32_t Ah[2][2][4], Al[2][2][4];
    uint32_t Bh[2][4][2], Bl[2][4][2];

    const int T = K / BK;

    // Prologue: tile 0 -> stage 0
    #pragma unroll
    for (int p = 0; p < 2; p++) {
        int row = ldrow + p * 64;
        float4 a = *reinterpret_cast<const float4*>(&X[(size_t)(bm + row) * K + ldkv * 4]);
        stage4(&AsH[0][0][0], &AsL[0][0][0], MSTR, ldkv * 2, row, a);
    }
    {
        float4 b = *reinterpret_cast<const float4*>(&W[(size_t)(bn + ldrow) * K + ldkv * 4]);
        stage4(&BsH[0][0][0], &BsL[0][0][0], NSTR, ldkv * 2, ldrow, b);
    }
    __syncthreads();

    #define LOAD_FRAG(buf, st)                                             \
        do {                                                               \
            _Pragma("unroll")                                              \
            for (int i = 0; i < 2; i++) {                                  \
                int row = wm * 32 + i * 16 + g;                            \
                Ah[buf][i][0] = AsH[st][tg    ][row];                      \
                Ah[buf][i][1] = AsH[st][tg    ][row + 8];                  \
                Ah[buf][i][2] = AsH[st][tg + 4][row];                      \
                Ah[buf][i][3] = AsH[st][tg + 4][row + 8];                  \
                Al[buf][i][0] = AsL[st][tg    ][row];                      \
                Al[buf][i][1] = AsL[st][tg    ][row + 8];                  \
                Al[buf][i][2] = AsL[st][tg + 4][row];                      \
                Al[buf][i][3] = AsL[st][tg + 4][row + 8];                  \
            }                                                              \
            _Pragma("unroll")                                              \
            for (int j = 0; j < 4; j++) {                                  \
                int col = wn * 32 + j * 8 + g;                             \
                Bh[buf][j][0] = BsH[st][tg    ][col];                      \
                Bh[buf][j][1] = BsH[st][tg + 4][col];                      \
                Bl[buf][j][0] = BsL[st][tg    ][col];                      \
                Bl[buf][j][1] = BsL[st][tg + 4][col];                      \
            }                                                              \
        } while (0)

    #define MMA_ALL(buf)                                                   \
        do {                                                               \
            _Pragma("unroll")                                              \
            for (int i = 0; i < 2; i++)                                    \
                _Pragma("unroll")                                          \
                for (int j = 0; j < 4; j++) {                              \
                    mma_bf16(acc[i][j],                                    \
                             Al[buf][i][0], Al[buf][i][1],                 \
                             Al[buf][i][2], Al[buf][i][3],                 \
                             Bh[buf][j][0], Bh[buf][j][1]);                \
                    mma_bf16(acc[i][j],                                    \
                             Ah[buf][i][0], Ah[buf][i][1],                 \
                             Ah[buf][i][2], Ah[buf][i][3],                 \
                             Bl[buf][j][0], Bl[buf][j][1]);                \
                    mma_bf16(acc[i][j],                                    \
                             Ah[buf][i][0], Ah[buf][i][1],                 \
                             Ah[buf][i][2], Ah[buf][i][3],                 \
                             Bh[buf][j][0], Bh[buf][j][1]);                \
                }                                                          \
        } while (0)

    LOAD_FRAG(0, 0);

    for (int t = 0; t < T; t++) {
        const int cur    = t & 1;
        const int nxt    = cur ^ 1;
        const int curbuf = t & 1;
        const int nxtbuf = curbuf ^ 1;

        // gmem prefetch for next tile (LDGs overlap the MMAs below)
        float4 pa[2], pb;
        if (t + 1 < T) {
            const int k0 = (t + 1) * BK;
            #pragma unroll
            for (int p = 0; p < 2; p++) {
                int row = ldrow + p * 64;
                pa[p] = *reinterpret_cast<const float4*>(&X[(size_t)(bm + row) * K + k0 + ldkv * 4]);
            }
            pb = *reinterpret_cast<const float4*>(&W[(size_t)(bn + ldrow) * K + k0 + ldkv * 4]);
        }

        MMA_ALL(curbuf);

        if (t + 1 < T) {
            #pragma unroll
            for (int p = 0; p < 2; p++)
                stage4(&AsH[nxt][0][0], &AsL[nxt][0][0], MSTR,
                       ldkv * 2, ldrow + p * 64, pa[p]);
            stage4(&BsH[nxt][0][0], &BsL[nxt][0][0], NSTR,
                   ldkv * 2, ldrow, pb);
            __syncthreads();
            LOAD_FRAG(nxtbuf, nxt);
        }
    }

    #undef LOAD_FRAG
    #undef MMA_ALL

    // Epilogue (same acc layout as m16n8k8)
    #pragma unroll
    for (int i = 0; i < 2; i++) {
        #pragma unroll
        for (int j = 0; j < 4; j++) {
            int row = bm + wm * 32 + i * 16 + g;
            int col = bn + wn * 32 + j * 8 + 2 * tg;
            float b0 = bias ? bias[col]     : 0.0f;
            float b1 = bias ? bias[col + 1] : 0.0f;
            float2 v0 = make_float2(acc[i][j][0] + b0, acc[i][j][1] + b1);
            float2 v1 = make_float2(acc[i][j][2] + b0, acc[i][j][3] + b1);
            *reinterpret_cast<float2*>(&Y[(size_t)row * N + col])       = v0;
            *reinterpret_cast<float2*>(&Y[(size_t)(row + 8) * N + col]) = v1;
        }
    }
}

// ---------------------------------------------------------------------------
// Fold Wo: Wf[e, g*D+d] = sum_{u=0..3} Wo[e, (4g+u)*D + d]
// ---------------------------------------------------------------------------
__global__ void fold_wo(const float* __restrict__ Wo, float* __restrict__ Wf)
{
    int i = blockIdx.x * blockDim.x + threadIdx.x;
    if (i >= Edim * KVdim) return;
    int e = i / KVdim;
    int c = i % KVdim;
    int gh = c / Ddim, d = c % Ddim;
    float s = 0.0f;
    #pragma unroll
    for (int u = 0; u < 4; u++)
        s += Wo[(size_t)e * KQVdim + (size_t)(gh * 4 + u) * Ddim + d];
    Wf[i] = s;
}

// ---------------------------------------------------------------------------
// Sliding-window GQA attention (flash-style), 4 distinct kv heads.
// ---------------------------------------------------------------------------
__global__ void __launch_bounds__(256, 2)
attn_window(const float* __restrict__ q, const float* __restrict__ k,
            const float* __restrict__ v, float* __restrict__ out)
{
    __shared__ float Qs[32][Ddim];
    __shared__ float Ks[Ddim][33];
    __shared__ float Vs[32][Ddim];

    const int tid  = threadIdx.x;
    const int warp = tid >> 5;
    const int lane = tid & 31;

    const int bh  = blockIdx.y;
    const int b   = bh / HKVdim;
    const int kvh = bh % HKVdim;
    const int q0  = blockIdx.x * 32;

    const float* qptr = q + ((size_t)b * Sdim + q0) * KVdim + kvh * Ddim;

    #pragma unroll
    for (int e = 0; e < 16; e++) {
        int lin = e * 256 + tid;
        int r = lin >> 7, d = lin & 127;
        Qs[r][d] = qptr[(size_t)r * KVdim + d];
    }

    float m[4], l[4], O[4][4];
    #pragma unroll
    for (int r = 0; r < 4; r++) {
        m[r] = -1e30f; l[r] = 0.0f;
        #pragma unroll
        for (int c = 0; c < 4; c++) O[r][c] = 0.0f;
    }

    int ktlo = q0 - (WIN - 1);
    if (ktlo < 0) ktlo = 0;
    ktlo = (ktlo / 32) * 32;

    for (int k0 = ktlo; k0 <= q0; k0 += 32) {
        const float* kptr = k + ((size_t)b * Sdim + k0) * KVdim + kvh * Ddim;
        const float* vptr = v + ((size_t)b * Sdim + k0) * KVdim + kvh * Ddim;
        __syncthreads();
        #pragma unroll
        for (int e = 0; e < 16; e++) {
            int lin = e * 256 + tid;
            int j = lin >> 7, d = lin & 127;
            Ks[d][j] = kptr[(size_t)j * KVdim + d];
            Vs[j][d] = vptr[(size_t)j * KVdim + d];
        }
        __syncthreads();

        #pragma unroll
        for (int r = 0; r < 4; r++) {
            const int row = warp * 4 + r;
            const int i   = q0 + row;
            const int jg  = k0 + lane;

            float s = 0.0f;
            #pragma unroll
            for (int d = 0; d < Ddim; d++)
                s = fmaf(Qs[row][d], Ks[d][lane], s);

            const bool valid = (jg <= i) && (jg > i - WIN);
            s = valid ? s : -1e30f;

            float mt = s;
            #pragma unroll
            for (int off = 16; off; off >>= 1)
                mt = fmaxf(mt, __shfl_xor_sync(0xffffffffu, mt, off));
            const float mnew  = fmaxf(m[r], mt);
            const float p     = valid ? __expf(s - mnew) : 0.0f;
            const float alpha = __expf(m[r] - mnew);
            m[r] = mnew;

            float rs = p;
            #pragma unroll
            for (int off = 16; off; off >>= 1)
                rs += __shfl_xor_sync(0xffffffffu, rs, off);
            l[r] = l[r] * alpha + rs;

            #pragma unroll
            for (int c = 0; c < 4; c++) O[r][c] *= alpha;
            #pragma unroll
            for (int j = 0; j < 32; j++) {
                const float pj = __shfl_sync(0xffffffffu, p, j);
                #pragma unroll
                for (int c = 0; c < 4; c++)
                    O[r][c] = fmaf(pj, Vs[j][c * 32 + lane], O[r][c]);
            }
        }
    }

    float* optr = out + ((size_t)b * Sdim + q0) * KVdim + kvh * Ddim;
    #pragma unroll
    for (int r = 0; r < 4; r++) {
        const int row = warp * 4 + r;
        const float inv = 1.0f / l[r];
        #pragma unroll
        for (int c = 0; c < 4; c++)
            optr[(size_t)row * KVdim + c * 32 + lane] = O[r][c] * inv;
    }
}

// ---------------------------------------------------------------------------
// Launch
// ---------------------------------------------------------------------------
extern "C" void kernel_launch(void* const* d_in, const int* in_sizes, int n_in,
                              void* d_out, int out_size)
{
    const float* x  = (const float*)d_in[0];
    const float* Wq = (const float*)d_in[1];   // only rows 0..511 used
    const float* Wk = (const float*)d_in[2];
    const float* Wv = (const float*)d_in[3];
    const float* Wo = (const float*)d_in[4];
    const float* bo = (const float*)d_in[5];
    float* out = (float*)d_out;

    float *qb, *kb, *vb, *ab, *wf;
    cudaGetSymbolAddress((void**)&qb, g_q);
    cudaGetSymbolAddress((void**)&kb, g_k);
    cudaGetSymbolAddress((void**)&vb, g_v);
    cudaGetSymbolAddress((void**)&ab, g_ao);
    cudaGetSymbolAddress((void**)&wf, g_wf);

    fold_wo<<<(Edim * KVdim + 255) / 256, 256>>>(Wo, wf);

    // Batched QKV projections (z selects weight/output)
    gemm_3xbf16<<<dim3(KVdim / BN, Mrows / BM, 3), 256>>>(
        x, Wq, Wk, Wv, qb, kb, vb, nullptr, KVdim, Edim);

    attn_window<<<dim3(Sdim / 32, Bdim * HKVdim), 256>>>(qb, kb, vb, ab);

    // Output projection with folded Wo + bias
    gemm_3xbf16<<<dim3(Edim / BN, Mrows / BM, 1), 256>>>(
        ab, wf, wf, wf, out, out, out, bo, Edim, KVdim);
}

// round 12
// speedup vs baseline: 1.4025x; 1.4025x over previous
#include <cuda_runtime.h>
#include <math.h>
#include <stdint.h>

// Problem constants
#define Bdim   2
#define Sdim   2048
#define Edim   2048
#define Hdim   16
#define HKVdim 4
#define Ddim   128
#define KQVdim 2048
#define KVdim  512            // HKV * D — compact Q / attn-out width
#define WIN    256
#define Mrows  (Bdim * Sdim)  // 4096

// Scratch (static __device__ — no allocation allowed)
__device__ float g_q [(size_t)Mrows * KVdim];
__device__ float g_k [(size_t)Mrows * KVdim];
__device__ float g_v [(size_t)Mrows * KVdim];
__device__ float g_ao[(size_t)Mrows * KVdim];
__device__ float g_wf[(size_t)Edim  * KVdim];    // folded Wo

// ---------------------------------------------------------------------------
// 3xTF32 tensor-core GEMM (fp32-accurate): Y = X @ W^T (+bias)
// BM=128, BN=64, BK=16, 256 threads (8 warps: 4 M x 2 N), 32x32/warp,
// 2 CTAs/SM. smem row-major [row][k] stride 20 (conflict-free fragments),
// filled by cp.async 16B (3-stage pipeline). hi/lo tf32 split in-register
// at fragment use (R9-proven arithmetic: rel_err 3.8e-5).
// ---------------------------------------------------------------------------
#define BM 128
#define BN 64
#define BK 16
#define KSTR 20                       // floats per row in smem
#define ASTG (BM * KSTR)              // 2560 words
#define BSTG (BN * KSTR)              // 1280 words
#define STG  (ASTG + BSTG)            // 3840 words per stage
// 3 stages * 3840 * 4B = 46080 B static smem

__device__ __forceinline__ uint32_t f2tf32(float f) {
    uint32_t r;
    asm("cvt.rna.tf32.f32 %0, %1;" : "=r"(r) : "f"(f));
    return r;
}

__device__ __forceinline__ void split2(float f, uint32_t& hi, uint32_t& lo) {
    hi = f2tf32(f);
    lo = __float_as_uint(f - __uint_as_float(hi));   // raw fp32; hw truncates
}

__device__ __forceinline__ void mma_tf32(float c[4], uint32_t a0, uint32_t a1,
                                         uint32_t a2, uint32_t a3,
                                         uint32_t b0, uint32_t b1) {
    asm volatile(
        "mma.sync.aligned.m16n8k8.row.col.f32.tf32.tf32.f32 "
        "{%0,%1,%2,%3}, {%4,%5,%6,%7}, {%8,%9}, {%0,%1,%2,%3};"
        : "+f"(c[0]), "+f"(c[1]), "+f"(c[2]), "+f"(c[3])
        : "r"(a0), "r"(a1), "r"(a2), "r"(a3), "r"(b0), "r"(b1));
}

__device__ __forceinline__ void cp_async16(uint32_t saddr, const float* g) {
    asm volatile("cp.async.ca.shared.global [%0], [%1], 16;"
                 :: "r"(saddr), "l"(g));
}

// Batched: gridDim.z selects (W, Y) pair. K fixed per launch.
__global__ void __launch_bounds__(256, 2)
gemm_3xtf32(const float* __restrict__ X,
            const float* __restrict__ W0, const float* __restrict__ W1,
            const float* __restrict__ W2,
            float* __restrict__ Y0, float* __restrict__ Y1,
            float* __restrict__ Y2,
            const float* __restrict__ bias,
            int N, int K)
{
    __shared__ float smbuf[3 * STG];

    const float* W = (blockIdx.z == 0) ? W0 : (blockIdx.z == 1) ? W1 : W2;
    float*       Y = (blockIdx.z == 0) ? Y0 : (blockIdx.z == 1) ? Y1 : Y2;

    const int tid  = threadIdx.x;
    const int warp = tid >> 5;
    const int lane = tid & 31;
    const int g    = lane >> 2;        // 0..7
    const int tg   = lane & 3;         // 0..3
    const int wm   = warp & 3;         // 0..3: 32 M-rows each
    const int wn   = warp >> 2;        // 0..1: 32 N-cols each
    const int bm   = blockIdx.y * BM;
    const int bn   = blockIdx.x * BN;

    const int ldrow = tid >> 2;        // 0..63
    const int ldkv  = tid & 3;         // 16B slot within BK

    const uint32_t smem_u32 =
        (uint32_t)__cvta_generic_to_shared(smbuf);

    float acc[2][4][4];
    #pragma unroll
    for (int i = 0; i < 2; i++)
        #pragma unroll
        for (int j = 0; j < 4; j++)
            #pragma unroll
            for (int c = 0; c < 4; c++) acc[i][j][c] = 0.0f;

    float Ar[2][2][4];
    float Br[2][4][2];

    const int T = K / BK;

    // Issue one tile's cp.asyncs into stage st (3 x 16B per thread)
    #define STAGE_ISSUE(st, k0)                                            \
        do {                                                               \
            const float* gA0 = &X[(size_t)(bm + ldrow)      * K + (k0) + ldkv * 4]; \
            const float* gA1 = &X[(size_t)(bm + ldrow + 64) * K + (k0) + ldkv * 4]; \
            const float* gB  = &W[(size_t)(bn + ldrow)      * K + (k0) + ldkv * 4]; \
            uint32_t b0 = smem_u32 + ((st) * STG) * 4;                     \
            cp_async16(b0 + (ldrow * KSTR + ldkv * 4) * 4, gA0);           \
            cp_async16(b0 + ((ldrow + 64) * KSTR + ldkv * 4) * 4, gA1);    \
            cp_async16(b0 + (ASTG + ldrow * KSTR + ldkv * 4) * 4, gB);     \
            asm volatile("cp.async.commit_group;");                        \
        } while (0)

    #define LOAD_FRAG(buf, st, ks)                                        \
        do {                                                              \
            const float* As = smbuf + (st) * STG;                         \
            const float* Bs = As + ASTG;                                  \
            _Pragma("unroll")                                             \
            for (int i = 0; i < 2; i++) {                                 \
                int row = wm * 32 + i * 16 + g;                           \
                Ar[buf][i][0] = As[row * KSTR + (ks) + tg];               \
                Ar[buf][i][1] = As[(row + 8) * KSTR + (ks) + tg];         \
                Ar[buf][i][2] = As[row * KSTR + (ks) + tg + 4];           \
                Ar[buf][i][3] = As[(row + 8) * KSTR + (ks) + tg + 4];     \
            }                                                             \
            _Pragma("unroll")                                             \
            for (int j = 0; j < 4; j++) {                                 \
                int col = wn * 32 + j * 8 + g;                            \
                Br[buf][j][0] = Bs[col * KSTR + (ks) + tg];               \
                Br[buf][j][1] = Bs[col * KSTR + (ks) + tg + 4];           \
            }                                                             \
        } while (0)

    #define MMA_ALL(buf)                                                   \
        do {                                                               \
            uint32_t bh[4][2], bl[4][2];                                   \
            _Pragma("unroll")                                              \
            for (int j = 0; j < 4; j++) {                                  \
                split2(Br[buf][j][0], bh[j][0], bl[j][0]);                 \
                split2(Br[buf][j][1], bh[j][1], bl[j][1]);                 \
            }                                                              \
            _Pragma("unroll")                                              \
            for (int i = 0; i < 2; i++) {                                  \
                uint32_t ah[4], al[4];                                     \
                _Pragma("unroll")                                          \
                for (int c = 0; c < 4; c++)                                \
                    split2(Ar[buf][i][c], ah[c], al[c]);                   \
                _Pragma("unroll")                                          \
                for (int j = 0; j < 4; j++) {                              \
                    mma_tf32(acc[i][j], al[0], al[1], al[2], al[3],        \
                             bh[j][0], bh[j][1]);                         \
                    mma_tf32(acc[i][j], ah[0], ah[1], ah[2], ah[3],        \
                             bl[j][0], bl[j][1]);                         \
                    mma_tf32(acc[i][j], ah[0], ah[1], ah[2], ah[3],        \
                             bh[j][0], bh[j][1]);                         \
                }                                                          \
            }                                                              \
        } while (0)

    // Prologue: tiles 0 and 1 in flight, wait for both, load frags of 0
    STAGE_ISSUE(0, 0);
    if (T > 1) STAGE_ISSUE(1, BK);
    asm volatile("cp.async.wait_group 0;");
    __syncthreads();
    LOAD_FRAG(0, 0, 0);

    int s_cur = 0;
    for (int t = 0; t < T; t++) {
        int s_nxt = s_cur + 1; if (s_nxt == 3) s_nxt = 0;
        int s_nn  = s_nxt + 1; if (s_nn  == 3) s_nn  = 0;

        if (t + 2 < T) STAGE_ISSUE(s_nn, (t + 2) * BK);

        LOAD_FRAG(1, s_cur, 8);
        MMA_ALL(0);

        if (t + 1 < T) {
            if (t + 2 < T) asm volatile("cp.async.wait_group 1;");
            else           asm volatile("cp.async.wait_group 0;");
            __syncthreads();
            LOAD_FRAG(0, s_nxt, 0);
        }
        MMA_ALL(1);
        s_cur = s_nxt;
    }

    #undef STAGE_ISSUE
    #undef LOAD_FRAG
    #undef MMA_ALL

    // Epilogue
    #pragma unroll
    for (int i = 0; i < 2; i++) {
        #pragma unroll
        for (int j = 0; j < 4; j++) {
            int row = bm + wm * 32 + i * 16 + g;
            int col = bn + wn * 32 + j * 8 + 2 * tg;
            float b0 = bias ? bias[col]     : 0.0f;
            float b1 = bias ? bias[col + 1] : 0.0f;
            float2 v0 = make_float2(acc[i][j][0] + b0, acc[i][j][1] + b1);
            float2 v1 = make_float2(acc[i][j][2] + b0, acc[i][j][3] + b1);
            *reinterpret_cast<float2*>(&Y[(size_t)row * N + col])       = v0;
            *reinterpret_cast<float2*>(&Y[(size_t)(row + 8) * N + col]) = v1;
        }
    }
}

// ---------------------------------------------------------------------------
// Fold Wo: Wf[e, g*D+d] = sum_{u=0..3} Wo[e, (4g+u)*D + d]
// ---------------------------------------------------------------------------
__global__ void fold_wo(const float* __restrict__ Wo, float* __restrict__ Wf)
{
    int i = blockIdx.x * blockDim.x + threadIdx.x;
    if (i >= Edim * KVdim) return;
    int e = i / KVdim;
    int c = i % KVdim;
    int gh = c / Ddim, d = c % Ddim;
    float s = 0.0f;
    #pragma unroll
    for (int u = 0; u < 4; u++)
        s += Wo[(size_t)e * KQVdim + (size_t)(gh * 4 + u) * Ddim + d];
    Wf[i] = s;
}

// ---------------------------------------------------------------------------
// Sliding-window GQA attention (flash-style), 4 distinct kv heads.
// ---------------------------------------------------------------------------
__global__ void __launch_bounds__(256, 2)
attn_window(const float* __restrict__ q, const float* __restrict__ k,
            const float* __restrict__ v, float* __restrict__ out)
{
    __shared__ float Qs[32][Ddim];
    __shared__ float Ks[Ddim][33];
    __shared__ float Vs[32][Ddim];

    const int tid  = threadIdx.x;
    const int warp = tid >> 5;
    const int lane = tid & 31;

    const int bh  = blockIdx.y;
    const int b   = bh / HKVdim;
    const int kvh = bh % HKVdim;
    const int q0  = blockIdx.x * 32;

    const float* qptr = q + ((size_t)b * Sdim + q0) * KVdim + kvh * Ddim;

    #pragma unroll
    for (int e = 0; e < 16; e++) {
        int lin = e * 256 + tid;
        int r = lin >> 7, d = lin & 127;
        Qs[r][d] = qptr[(size_t)r * KVdim + d];
    }

    float m[4], l[4], O[4][4];
    #pragma unroll
    for (int r = 0; r < 4; r++) {
        m[r] = -1e30f; l[r] = 0.0f;
        #pragma unroll
        for (int c = 0; c < 4; c++) O[r][c] = 0.0f;
    }

    int ktlo = q0 - (WIN - 1);
    if (ktlo < 0) ktlo = 0;
    ktlo = (ktlo / 32) * 32;

    for (int k0 = ktlo; k0 <= q0; k0 += 32) {
        const float* kptr = k + ((size_t)b * Sdim + k0) * KVdim + kvh * Ddim;
        const float* vptr = v + ((size_t)b * Sdim + k0) * KVdim + kvh * Ddim;
        __syncthreads();
        #pragma unroll
        for (int e = 0; e < 16; e++) {
            int lin = e * 256 + tid;
            int j = lin >> 7, d = lin & 127;
            Ks[d][j] = kptr[(size_t)j * KVdim + d];
            Vs[j][d] = vptr[(size_t)j * KVdim + d];
        }
        __syncthreads();

        #pragma unroll
        for (int r = 0; r < 4; r++) {
            const int row = warp * 4 + r;
            const int i   = q0 + row;
            const int jg  = k0 + lane;

            float s = 0.0f;
            #pragma unroll
            for (int d = 0; d < Ddim; d++)
                s = fmaf(Qs[row][d], Ks[d][lane], s);

            const bool valid = (jg <= i) && (jg > i - WIN);
            s = valid ? s : -1e30f;

            float mt = s;
            #pragma unroll
            for (int off = 16; off; off >>= 1)
                mt = fmaxf(mt, __shfl_xor_sync(0xffffffffu, mt, off));
            const float mnew  = fmaxf(m[r], mt);
            const float p     = valid ? __expf(s - mnew) : 0.0f;
            const float alpha = __expf(m[r] - mnew);
            m[r] = mnew;

            float rs = p;
            #pragma unroll
            for (int off = 16; off; off >>= 1)
                rs += __shfl_xor_sync(0xffffffffu, rs, off);
            l[r] = l[r] * alpha + rs;

            #pragma unroll
            for (int c = 0; c < 4; c++) O[r][c] *= alpha;
            #pragma unroll
            for (int j = 0; j < 32; j++) {
                const float pj = __shfl_sync(0xffffffffu, p, j);
                #pragma unroll
                for (int c = 0; c < 4; c++)
                    O[r][c] = fmaf(pj, Vs[j][c * 32 + lane], O[r][c]);
            }
        }
    }

    float* optr = out + ((size_t)b * Sdim + q0) * KVdim + kvh * Ddim;
    #pragma unroll
    for (int r = 0; r < 4; r++) {
        const int row = warp * 4 + r;
        const float inv = 1.0f / l[r];
        #pragma unroll
        for (int c = 0; c < 4; c++)
            optr[(size_t)row * KVdim + c * 32 + lane] = O[r][c] * inv;
    }
}

// ---------------------------------------------------------------------------
// Launch
// ---------------------------------------------------------------------------
extern "C" void kernel_launch(void* const* d_in, const int* in_sizes, int n_in,
                              void* d_out, int out_size)
{
    const float* x  = (const float*)d_in[0];
    const float* Wq = (const float*)d_in[1];   // only rows 0..511 used
    const float* Wk = (const float*)d_in[2];
    const float* Wv = (const float*)d_in[3];
    const float* Wo = (const float*)d_in[4];
    const float* bo = (const float*)d_in[5];
    float* out = (float*)d_out;

    float *qb, *kb, *vb, *ab, *wf;
    cudaGetSymbolAddress((void**)&qb, g_q);
    cudaGetSymbolAddress((void**)&kb, g_k);
    cudaGetSymbolAddress((void**)&vb, g_v);
    cudaGetSymbolAddress((void**)&ab, g_ao);
    cudaGetSymbolAddress((void**)&wf, g_wf);

    fold_wo<<<(Edim * KVdim + 255) / 256, 256>>>(Wo, wf);

    // Batched QKV projections (z selects weight/output)
    gemm_3xtf32<<<dim3(KVdim / BN, Mrows / BM, 3), 256>>>(
        x, Wq, Wk, Wv, qb, kb, vb, nullptr, KVdim, Edim);

    attn_window<<<dim3(Sdim / 32, Bdim * HKVdim), 256>>>(qb, kb, vb, ab);

    // Output projection with folded Wo + bias
    gemm_3xtf32<<<dim3(Edim / BN, Mrows / BM, 1), 256>>>(
        ab, wf, wf, wf, out, out, out, bo, Edim, KVdim);
}

// round 15
// speedup vs baseline: 1.4560x; 1.0382x over previous
#include <cuda_runtime.h>
#include <math.h>
#include <stdint.h>

// Problem constants
#define Bdim   2
#define Sdim   2048
#define Edim   2048
#define Hdim   16
#define HKVdim 4
#define Ddim   128
#define KQVdim 2048
#define KVdim  512            // HKV * D — compact Q / attn-out width
#define WIN    256
#define Mrows  (Bdim * Sdim)  // 4096

// Scratch (static __device__ — no allocation allowed)
__device__ float g_q [(size_t)Mrows * KVdim];
__device__ float g_k [(size_t)Mrows * KVdim];
__device__ float g_v [(size_t)Mrows * KVdim];
__device__ float g_ao[(size_t)Mrows * KVdim];
__device__ float g_wf[(size_t)Edim  * KVdim];    // folded Wo

// ---------------------------------------------------------------------------
// 3xBF16 tensor-core GEMM (fp32-accurate): Y = X @ W^T (+bias)
// BM=128, BN=64, BK=16, 256 threads (8 warps: 4 M x 2 N), 32x32/warp,
// 2 CTAs/SM. smem holds PACKED bf16x2 hi/lo planes, stride 136/72
// (bank = 8*tg + g -> conflict-free fragment loads). Split once at staging.
// Mainloop: 32 LDS.32 + 24 mma.m16n8k16.bf16 per warp per K=16.
// Gmem prefetch DISTANCE 2 (tile t+2 issued at iter t).
// acc += Alo*Bhi + Ahi*Blo + Ahi*Bhi   (dropped Alo*Blo ~ 2^-18 rel)
// ---------------------------------------------------------------------------
#define BM 128
#define BN 64
#define BK 16
#define MSTR 136   // bf16x2 words per k-pair row (A)
#define NSTR 72    // (B)

// pack two floats as bf16x2: low 16 = e0 (even k), high 16 = e1 (odd k)
__device__ __forceinline__ uint32_t packbf(float e0, float e1) {
    uint32_t r;
    asm("cvt.rn.bf16x2.f32 %0, %1, %2;" : "=r"(r) : "f"(e1), "f"(e0));
    return r;
}

__device__ __forceinline__ void mma_bf16(float c[4], uint32_t a0, uint32_t a1,
                                         uint32_t a2, uint32_t a3,
                                         uint32_t b0, uint32_t b1) {
    asm volatile(
        "mma.sync.aligned.m16n8k16.row.col.f32.bf16.bf16.f32 "
        "{%0,%1,%2,%3}, {%4,%5,%6,%7}, {%8,%9}, {%0,%1,%2,%3};"
        : "+f"(c[0]), "+f"(c[1]), "+f"(c[2]), "+f"(c[3])
        : "r"(a0), "r"(a1), "r"(a2), "r"(a3), "r"(b0), "r"(b1));
}

// Split float4 (4 consecutive k of one row) into hi/lo bf16x2 and store.
__device__ __forceinline__ void stage4(uint32_t* hiP, uint32_t* loP,
                                       int stride, int pairbase, int row,
                                       float4 v) {
    uint32_t h01 = packbf(v.x, v.y);
    uint32_t h23 = packbf(v.z, v.w);
    float lx = v.x - __uint_as_float(h01 << 16);
    float ly = v.y - __uint_as_float(h01 & 0xffff0000u);
    float lz = v.z - __uint_as_float(h23 << 16);
    float lw = v.w - __uint_as_float(h23 & 0xffff0000u);
    hiP[(pairbase + 0) * stride + row] = h01;
    hiP[(pairbase + 1) * stride + row] = h23;
    loP[(pairbase + 0) * stride + row] = packbf(lx, ly);
    loP[(pairbase + 1) * stride + row] = packbf(lz, lw);
}

// Batched: gridDim.z selects (W, Y) pair. K fixed per launch.
__global__ void __launch_bounds__(256, 2)
gemm_3xbf16(const float* __restrict__ X,
            const float* __restrict__ W0, const float* __restrict__ W1,
            const float* __restrict__ W2,
            float* __restrict__ Y0, float* __restrict__ Y1,
            float* __restrict__ Y2,
            const float* __restrict__ bias,
            int N, int K)
{
    __shared__ uint32_t AsH[2][8][MSTR];
    __shared__ uint32_t AsL[2][8][MSTR];
    __shared__ uint32_t BsH[2][8][NSTR];
    __shared__ uint32_t BsL[2][8][NSTR];

    const float* W = (blockIdx.z == 0) ? W0 : (blockIdx.z == 1) ? W1 : W2;
    float*       Y = (blockIdx.z == 0) ? Y0 : (blockIdx.z == 1) ? Y1 : Y2;

    const int tid  = threadIdx.x;
    const int warp = tid >> 5;
    const int lane = tid & 31;
    const int g    = lane >> 2;        // 0..7
    const int tg   = lane & 3;         // 0..3
    const int wm   = warp & 3;         // 0..3: 32 M-rows each
    const int wn   = warp >> 2;        // 0..1: 32 N-cols each
    const int bm   = blockIdx.y * BM;
    const int bn   = blockIdx.x * BN;

    const int ldrow = tid >> 2;        // 0..63
    const int ldkv  = tid & 3;         // float4 slot within BK=16

    float acc[2][4][4];
    #pragma unroll
    for (int i = 0; i < 2; i++)
        #pragma unroll
        for (int j = 0; j < 4; j++)
            #pragma unroll
            for (int c = 0; c < 4; c++) acc[i][j][c] = 0.0f;

    // bf16x2 fragments (single buffer: MMA consumes before reload)
    uint32_t Ah[2][4], Al[2][4];
    uint32_t Bh[4][2], Bl[4][2];

    // distance-2 gmem prefetch register buffers (by tile parity)
    float4 rpa[2][2], rpb[2];

    const int T = K / BK;

    #define LDG_TILE(par, k0)                                              \
        do {                                                               \
            rpa[par][0] = *reinterpret_cast<const float4*>(                \
                &X[(size_t)(bm + ldrow)      * K + (k0) + ldkv * 4]);      \
            rpa[par][1] = *reinterpret_cast<const float4*>(                \
                &X[(size_t)(bm + ldrow + 64) * K + (k0) + ldkv * 4]);      \
            rpb[par]    = *reinterpret_cast<const float4*>(                \
                &W[(size_t)(bn + ldrow)      * K + (k0) + ldkv * 4]);      \
        } while (0)

    #define STS_TILE(par)                                                  \
        do {                                                               \
            stage4(&AsH[par][0][0], &AsL[par][0][0], MSTR,                 \
                   ldkv * 2, ldrow,      rpa[par][0]);                     \
            stage4(&AsH[par][0][0], &AsL[par][0][0], MSTR,                 \
                   ldkv * 2, ldrow + 64, rpa[par][1]);                     \
            stage4(&BsH[par][0][0], &BsL[par][0][0], NSTR,                 \
                   ldkv * 2, ldrow,      rpb[par]);                        \
        } while (0)

    #define LOAD_FRAG(st)                                                  \
        do {                                                               \
            _Pragma("unroll")                                              \
            for (int i = 0; i < 2; i++) {                                  \
                int row = wm * 32 + i * 16 + g;                            \
                Ah[i][0] = AsH[st][tg    ][row];                           \
                Ah[i][1] = AsH[st][tg    ][row + 8];                       \
                Ah[i][2] = AsH[st][tg + 4][row];                           \
                Ah[i][3] = AsH[st][tg + 4][row + 8];                       \
                Al[i][0] = AsL[st][tg    ][row];                           \
                Al[i][1] = AsL[st][tg    ][row + 8];                       \
                Al[i][2] = AsL[st][tg + 4][row];                           \
                Al[i][3] = AsL[st][tg + 4][row + 8];                       \
            }                                                              \
            _Pragma("unroll")                                              \
            for (int j = 0; j < 4; j++) {                                  \
                int col = wn * 32 + j * 8 + g;                             \
                Bh[j][0] = BsH[st][tg    ][col];                           \
                Bh[j][1] = BsH[st][tg + 4][col];                           \
                Bl[j][0] = BsL[st][tg    ][col];                           \
                Bl[j][1] = BsL[st][tg + 4][col];                           \
            }                                                              \
        } while (0)

    #define MMA_ALL()                                                      \
        do {                                                               \
            _Pragma("unroll")                                              \
            for (int i = 0; i < 2; i++)                                    \
                _Pragma("unroll")                                          \
                for (int j = 0; j < 4; j++) {                              \
                    mma_bf16(acc[i][j], Al[i][0], Al[i][1],                \
                             Al[i][2], Al[i][3], Bh[j][0], Bh[j][1]);      \
                    mma_bf16(acc[i][j], Ah[i][0], Ah[i][1],                \
                             Ah[i][2], Ah[i][3], Bl[j][0], Bl[j][1]);      \
                    mma_bf16(acc[i][j], Ah[i][0], Ah[i][1],                \
                             Ah[i][2], Ah[i][3], Bh[j][0], Bh[j][1]);      \
                }                                                          \
        } while (0)

    // Prologue: tile 0 staged directly; tile 1 into regbuf parity 1.
    LDG_TILE(0, 0);
    STS_TILE(0);        // tile0 -> stage 0 (parity 0)
    if (T > 1) LDG_TILE(1, BK);
    __syncthreads();
    LOAD_FRAG(0);

    for (int t = 0; t < T; t++) {
        const int par  = t & 1;
        const int npar = par ^ 1;

        // distance-2 prefetch: tile t+2 into regbuf[par] (free after STS at t-1)
        if (t + 2 < T) LDG_TILE(par, (t + 2) * BK);

        MMA_ALL();   // tile t (fragments already in registers)

        if (t + 1 < T) {
            STS_TILE(npar);          // tile t+1 -> stage npar
            __syncthreads();
            LOAD_FRAG(npar);         // fragments for tile t+1
        }
    }

    #undef LDG_TILE
    #undef STS_TILE
    #undef LOAD_FRAG
    #undef MMA_ALL

    // Epilogue (c0,c1 -> row, 2tg..; c2,c3 -> row+8)
    #pragma unroll
    for (int i = 0; i < 2; i++) {
        #pragma unroll
        for (int j = 0; j < 4; j++) {
            int row = bm + wm * 32 + i * 16 + g;
            int col = bn + wn * 32 + j * 8 + 2 * tg;
            float b0 = bias ? bias[col]     : 0.0f;
            float b1 = bias ? bias[col + 1] : 0.0f;
            float2 v0 = make_float2(acc[i][j][0] + b0, acc[i][j][1] + b1);
            float2 v1 = make_float2(acc[i][j][2] + b0, acc[i][j][3] + b1);
            *reinterpret_cast<float2*>(&Y[(size_t)row * N + col])       = v0;
            *reinterpret_cast<float2*>(&Y[(size_t)(row + 8) * N + col]) = v1;
        }
    }
}

// ---------------------------------------------------------------------------
// Fold Wo: Wf[e, g*D+d] = sum_{u=0..3} Wo[e, (4g+u)*D + d]
// ---------------------------------------------------------------------------
__global__ void fold_wo(const float* __restrict__ Wo, float* __restrict__ Wf)
{
    int i = blockIdx.x * blockDim.x + threadIdx.x;
    if (i >= Edim * KVdim) return;
    int e = i / KVdim;
    int c = i % KVdim;
    int gh = c / Ddim, d = c % Ddim;
    float s = 0.0f;
    #pragma unroll
    for (int u = 0; u < 4; u++)
        s += Wo[(size_t)e * KQVdim + (size_t)(gh * 4 + u) * Ddim + d];
    Wf[i] = s;
}

// ---------------------------------------------------------------------------
// Sliding-window GQA attention (flash-style), 4 distinct kv heads.
// ---------------------------------------------------------------------------
__global__ void __launch_bounds__(256, 2)
attn_window(const float* __restrict__ q, const float* __restrict__ k,
            const float* __restrict__ v, float* __restrict__ out)
{
    __shared__ float Qs[32][Ddim];
    __shared__ float Ks[Ddim][33];
    __shared__ float Vs[32][Ddim];

    const int tid  = threadIdx.x;
    const int warp = tid >> 5;
    const int lane = tid & 31;

    const int bh  = blockIdx.y;
    const int b   = bh / HKVdim;
    const int kvh = bh % HKVdim;
    const int q0  = blockIdx.x * 32;

    const float* qptr = q + ((size_t)b * Sdim + q0) * KVdim + kvh * Ddim;

    #pragma unroll
    for (int e = 0; e < 16; e++) {
        int lin = e * 256 + tid;
        int r = lin >> 7, d = lin & 127;
        Qs[r][d] = qptr[(size_t)r * KVdim + d];
    }

    float m[4], l[4], O[4][4];
    #pragma unroll
    for (int r = 0; r < 4; r++) {
        m[r] = -1e30f; l[r] = 0.0f;
        #pragma unroll
        for (int c = 0; c < 4; c++) O[r][c] = 0.0f;
    }

    int ktlo = q0 - (WIN - 1);
    if (ktlo < 0) ktlo = 0;
    ktlo = (ktlo / 32) * 32;

    for (int k0 = ktlo; k0 <= q0; k0 += 32) {
        const float* kptr = k + ((size_t)b * Sdim + k0) * KVdim + kvh * Ddim;
        const float* vptr = v + ((size_t)b * Sdim + k0) * KVdim + kvh * Ddim;
        __syncthreads();
        #pragma unroll
        for (int e = 0; e < 16; e++) {
            int lin = e * 256 + tid;
            int j = lin >> 7, d = lin & 127;
            Ks[d][j] = kptr[(size_t)j * KVdim + d];
            Vs[j][d] = vptr[(size_t)j * KVdim + d];
        }
        __syncthreads();

        #pragma unroll
        for (int r = 0; r < 4; r++) {
            const int row = warp * 4 + r;
            const int i   = q0 + row;
            const int jg  = k0 + lane;

            float s = 0.0f;
            #pragma unroll
            for (int d = 0; d < Ddim; d++)
                s = fmaf(Qs[row][d], Ks[d][lane], s);

            const bool valid = (jg <= i) && (jg > i - WIN);
            s = valid ? s : -1e30f;

            float mt = s;
            #pragma unroll
            for (int off = 16; off; off >>= 1)
                mt = fmaxf(mt, __shfl_xor_sync(0xffffffffu, mt, off));
            const float mnew  = fmaxf(m[r], mt);
            const float p     = valid ? __expf(s - mnew) : 0.0f;
            const float alpha = __expf(m[r] - mnew);
            m[r] = mnew;

            float rs = p;
            #pragma unroll
            for (int off = 16; off; off >>= 1)
                rs += __shfl_xor_sync(0xffffffffu, rs, off);
            l[r] = l[r] * alpha + rs;

            #pragma unroll
            for (int c = 0; c < 4; c++) O[r][c] *= alpha;
            #pragma unroll
            for (int j = 0; j < 32; j++) {
                const float pj = __shfl_sync(0xffffffffu, p, j);
                #pragma unroll
                for (int c = 0; c < 4; c++)
                    O[r][c] = fmaf(pj, Vs[j][c * 32 + lane], O[r][c]);
            }
        }
    }

    float* optr = out + ((size_t)b * Sdim + q0) * KVdim + kvh * Ddim;
    #pragma unroll
    for (int r = 0; r < 4; r++) {
        const int row = warp * 4 + r;
        const float inv = 1.0f / l[r];
        #pragma unroll
        for (int c = 0; c < 4; c++)
            optr[(size_t)row * KVdim + c * 32 + lane] = O[r][c] * inv;
    }
}

// ---------------------------------------------------------------------------
// Launch
// ---------------------------------------------------------------------------
extern "C" void kernel_launch(void* const* d_in, const int* in_sizes, int n_in,
                              void* d_out, int out_size)
{
    const float* x  = (const float*)d_in[0];
    const float* Wq = (const float*)d_in[1];   // only rows 0..511 used
    const float* Wk = (const float*)d_in[2];
    const float* Wv = (const float*)d_in[3];
    const float* Wo = (const float*)d_in[4];
    const float* bo = (const float*)d_in[5];
    float* out = (float*)d_out;

    float *qb, *kb, *vb, *ab, *wf;
    cudaGetSymbolAddress((void**)&qb, g_q);
    cudaGetSymbolAddress((void**)&kb, g_k);
    cudaGetSymbolAddress((void**)&vb, g_v);
    cudaGetSymbolAddress((void**)&ab, g_ao);
    cudaGetSymbolAddress((void**)&wf, g_wf);

    fold_wo<<<(Edim * KVdim + 255) / 256, 256>>>(Wo, wf);

    // Batched QKV projections (z selects weight/output)
    gemm_3xbf16<<<dim3(KVdim / BN, Mrows / BM, 3), 256>>>(
        x, Wq, Wk, Wv, qb, kb, vb, nullptr, KVdim, Edim);

    attn_window<<<dim3(Sdim / 32, Bdim * HKVdim), 256>>>(qb, kb, vb, ab);

    // Output projection with folded Wo + bias
    gemm_3xbf16<<<dim3(Edim / BN, Mrows / BM, 1), 256>>>(
        ab, wf, wf, wf, out, out, out, bo, Edim, KVdim);
}

// round 17
// speedup vs baseline: 1.8227x; 1.2519x over previous
#include <cuda_runtime.h>
#include <cuda_bf16.h>
#include <math.h>
#include <stdint.h>

// Problem constants
#define Bdim   2
#define Sdim   2048
#define Edim   2048
#define HKVdim 4
#define Ddim   128
#define KQVdim 2048
#define KVdim  512
#define WIN    256
#define Mrows  4096
#define NQKV   1536            // used-Q(512)+K(512)+V(512)

// fp32 intermediates
__device__ float g_q [(size_t)Mrows * KVdim];
__device__ float g_k [(size_t)Mrows * KVdim];
__device__ float g_v [(size_t)Mrows * KVdim];
__device__ float g_ao[(size_t)Mrows * KVdim];

// bf16 hi/lo planes
__device__ __nv_bfloat16 g_xh [(size_t)Mrows * Edim];
__device__ __nv_bfloat16 g_xl [(size_t)Mrows * Edim];
__device__ __nv_bfloat16 g_wh [(size_t)NQKV  * Edim];
__device__ __nv_bfloat16 g_wl [(size_t)NQKV  * Edim];
__device__ __nv_bfloat16 g_fh [(size_t)Edim  * KVdim];
__device__ __nv_bfloat16 g_fl [(size_t)Edim  * KVdim];
__device__ __nv_bfloat16 g_aoh[(size_t)Mrows * KVdim];
__device__ __nv_bfloat16 g_aol[(size_t)Mrows * KVdim];

// ---------------------------------------------------------------------------
// Conversions: hi = bf16(x), lo = bf16(x - hi)
// ---------------------------------------------------------------------------
__device__ __forceinline__ void split_bf(float x, __nv_bfloat16& h, __nv_bfloat16& l) {
    h = __float2bfloat16(x);
    l = __float2bfloat16(x - __bfloat162float(h));
}

__global__ void cvt_split(const float* __restrict__ src,
                          __nv_bfloat16* __restrict__ hi,
                          __nv_bfloat16* __restrict__ lo, int n)
{
    int i = blockIdx.x * 256 + threadIdx.x;
    if (i >= n) return;
    split_bf(src[i], hi[i], lo[i]);
}

__global__ void cvt_w(const float* __restrict__ Wq, const float* __restrict__ Wk,
                      const float* __restrict__ Wv,
                      __nv_bfloat16* __restrict__ hi, __nv_bfloat16* __restrict__ lo)
{
    int i = blockIdx.x * 256 + threadIdx.x;
    if (i >= NQKV * Edim) return;
    int r = i / Edim, c = i % Edim;
    const float* row = (r < 512) ? Wq + (size_t)r * Edim
                    : (r < 1024) ? Wk + (size_t)(r - 512) * Edim
                                 : Wv + (size_t)(r - 1024) * Edim;
    split_bf(row[c], hi[i], lo[i]);
}

__global__ void fold_cvt(const float* __restrict__ Wo,
                         __nv_bfloat16* __restrict__ hi, __nv_bfloat16* __restrict__ lo)
{
    int i = blockIdx.x * 256 + threadIdx.x;
    if (i >= Edim * KVdim) return;
    int e = i / KVdim, c = i % KVdim;
    int gh = c / Ddim, d = c % Ddim;
    float s = 0.0f;
    #pragma unroll
    for (int u = 0; u < 4; u++)
        s += Wo[(size_t)e * KQVdim + (size_t)(gh * 4 + u) * Ddim + d];
    split_bf(s, hi[i], lo[i]);
}

// ---------------------------------------------------------------------------
// 3xBF16 mma.sync GEMM reading pre-split gmem planes via cp.async 3-stage ring.
// BM=128, BN=64, BK=32 (2 K16 halves), 256 thr (8 warps 4Mx2N), 32x32/warp.
// smem row-major [row][kpair], stride 20 words (bank 20g+tg: conflict-free,
// 16B-aligned rows for cp.async). One __syncthreads per K=32.
// acc += Alo*Bhi + Ahi*Blo + Ahi*Bhi
// ---------------------------------------------------------------------------
#define BM 128
#define BN 64
#define BK 32
#define RSTR 20                        // bf16x2 words per row
#define AW (BM * RSTR)                 // 2560 words
#define BW (BN * RSTR)                 // 1280 words
#define STGW (2 * AW + 2 * BW)         // 7680 words per stage (AH,AL,BH,BL)
#define SMEM_TOT (3 * STGW * 4)        // 92160 B
#define OFF_AH 0
#define OFF_AL AW
#define OFF_BH (2 * AW)
#define OFF_BL (2 * AW + BW)

__device__ __forceinline__ void mma_bf16(float c[4], uint32_t a0, uint32_t a1,
                                         uint32_t a2, uint32_t a3,
                                         uint32_t b0, uint32_t b1) {
    asm volatile(
        "mma.sync.aligned.m16n8k16.row.col.f32.bf16.bf16.f32 "
        "{%0,%1,%2,%3}, {%4,%5,%6,%7}, {%8,%9}, {%0,%1,%2,%3};"
        : "+f"(c[0]), "+f"(c[1]), "+f"(c[2]), "+f"(c[3])
        : "r"(a0), "r"(a1), "r"(a2), "r"(a3), "r"(b0), "r"(b1));
}

__global__ void __launch_bounds__(256, 2)
gemm_ps(const __nv_bfloat16* __restrict__ aH, const __nv_bfloat16* __restrict__ aL,
        const __nv_bfloat16* __restrict__ bH, const __nv_bfloat16* __restrict__ bL,
        float* __restrict__ Y0, float* __restrict__ Y1, float* __restrict__ Y2,
        const float* __restrict__ bias, int K, int splitN, int Ystr)
{
    extern __shared__ uint32_t sm[];
    const uint32_t smem_u32 = (uint32_t)__cvta_generic_to_shared(sm);

    const int tid  = threadIdx.x;
    const int warp = tid >> 5;
    const int lane = tid & 31;
    const int g    = lane >> 2;        // 0..7
    const int tg   = lane & 3;         // 0..3
    const int wm   = warp & 3;         // 0..3
    const int wn   = warp >> 2;        // 0..1
    const int bm   = blockIdx.y * BM;
    const int bn   = blockIdx.x * BN;

    float acc[2][4][4];
    #pragma unroll
    for (int i = 0; i < 2; i++)
        #pragma unroll
        for (int j = 0; j < 4; j++)
            #pragma unroll
            for (int c = 0; c < 4; c++) acc[i][j][c] = 0.0f;

    // fragment double-buffers (per K16 half)
    uint32_t Ah[2][2][4], Al[2][2][4];
    uint32_t Bh[2][4][2], Bl[2][4][2];

    const int T = K / BK;

    // cp.async one tile into stage st: 6 x 16B per thread
    #define STAGE_ISSUE(st, k0)                                               \
        do {                                                                  \
            uint32_t base = smem_u32 + (st) * STGW * 4;                       \
            _Pragma("unroll")                                                 \
            for (int i6 = 0; i6 < 6; i6++) {                                  \
                int idx = i6 * 256 + tid;                                     \
                const __nv_bfloat16* src;                                     \
                uint32_t dst;                                                 \
                if (idx < 1024) {                                             \
                    int pl = idx >> 9, rc = idx & 511;                        \
                    int row = rc >> 2, slot = rc & 3;                         \
                    src = (pl ? aL : aH) + (size_t)(bm + row) * K + (k0) + slot * 8; \
                    dst = base + ((pl ? OFF_AL : OFF_AH) + row * RSTR + slot * 4) * 4; \
                } else {                                                      \
                    int x2 = idx - 1024;                                      \
                    int pl = x2 >> 8, rc = x2 & 255;                          \
                    int row = rc >> 2, slot = rc & 3;                         \
                    src = (pl ? bL : bH) + (size_t)(bn + row) * K + (k0) + slot * 8; \
                    dst = base + ((pl ? OFF_BL : OFF_BH) + row * RSTR + slot * 4) * 4; \
                }                                                             \
                asm volatile("cp.async.ca.shared.global [%0], [%1], 16;"      \
                             :: "r"(dst), "l"(src));                          \
            }                                                                 \
            asm volatile("cp.async.commit_group;");                           \
        } while (0)

    #define LOAD_FRAG(buf, st, half)                                          \
        do {                                                                  \
            const uint32_t* As = sm + (st) * STGW;                            \
            const uint32_t* AsL_ = As + OFF_AL;                               \
            const uint32_t* BsH_ = As + OFF_BH;                               \
            const uint32_t* BsL_ = As + OFF_BL;                               \
            const int kb = (half) * 8;                                        \
            _Pragma("unroll")                                                 \
            for (int i = 0; i < 2; i++) {                                     \
                int row = wm * 32 + i * 16 + g;                               \
                Ah[buf][i][0] = As  [row * RSTR + kb + tg];                   \
                Ah[buf][i][1] = As  [(row + 8) * RSTR + kb + tg];             \
                Ah[buf][i][2] = As  [row * RSTR + kb + tg + 4];               \
                Ah[buf][i][3] = As  [(row + 8) * RSTR + kb + tg + 4];         \
                Al[buf][i][0] = AsL_[row * RSTR + kb + tg];                   \
                Al[buf][i][1] = AsL_[(row + 8) * RSTR + kb + tg];             \
                Al[buf][i][2] = AsL_[row * RSTR + kb + tg + 4];               \
                Al[buf][i][3] = AsL_[(row + 8) * RSTR + kb + tg + 4];         \
            }                                                                 \
            _Pragma("unroll")                                                 \
            for (int j = 0; j < 4; j++) {                                     \
                int col = wn * 32 + j * 8 + g;                                \
                Bh[buf][j][0] = BsH_[col * RSTR + kb + tg];                   \
                Bh[buf][j][1] = BsH_[col * RSTR + kb + tg + 4];               \
                Bl[buf][j][0] = BsL_[col * RSTR + kb + tg];                   \
                Bl[buf][j][1] = BsL_[col * RSTR + kb + tg + 4];               \
            }                                                                 \
        } while (0)

    #define MMA_ALL(buf)                                                      \
        do {                                                                  \
            _Pragma("unroll")                                                 \
            for (int i = 0; i < 2; i++)                                       \
                _Pragma("unroll")                                             \
                for (int j = 0; j < 4; j++) {                                 \
                    mma_bf16(acc[i][j], Al[buf][i][0], Al[buf][i][1],         \
                             Al[buf][i][2], Al[buf][i][3],                    \
                             Bh[buf][j][0], Bh[buf][j][1]);                   \
                    mma_bf16(acc[i][j], Ah[buf][i][0], Ah[buf][i][1],         \
                             Ah[buf][i][2], Ah[buf][i][3],                    \
                             Bl[buf][j][0], Bl[buf][j][1]);                   \
                    mma_bf16(acc[i][j], Ah[buf][i][0], Ah[buf][i][1],         \
                             Ah[buf][i][2], Ah[buf][i][3],                    \
                             Bh[buf][j][0], Bh[buf][j][1]);                   \
                }                                                             \
        } while (0)

    // Prologue: tiles 0,1 in flight; wait tile 0; frags(half0)
    STAGE_ISSUE(0, 0);
    if (T > 1) STAGE_ISSUE(1, BK);
    if (T > 1) asm volatile("cp.async.wait_group 1;" ::: "memory");
    else       asm volatile("cp.async.wait_group 0;" ::: "memory");
    __syncthreads();
    LOAD_FRAG(0, 0, 0);

    int s_cur = 0;
    for (int t = 0; t < T; t++) {
        int s_nxt = s_cur + 1; if (s_nxt == 3) s_nxt = 0;
        int s_nn  = s_nxt + 1; if (s_nn  == 3) s_nn  = 0;

        if (t + 2 < T) STAGE_ISSUE(s_nn, (t + 2) * BK);

        LOAD_FRAG(1, s_cur, 1);   // half1 of current tile
        MMA_ALL(0);               // half0

        if (t + 1 < T) {
            if (t + 2 < T) asm volatile("cp.async.wait_group 1;" ::: "memory");
            else           asm volatile("cp.async.wait_group 0;" ::: "memory");
            __syncthreads();
            LOAD_FRAG(0, s_nxt, 0);   // half0 of next tile
        }
        MMA_ALL(1);               // half1
        s_cur = s_nxt;
    }

    #undef STAGE_ISSUE
    #undef LOAD_FRAG
    #undef MMA_ALL

    // Epilogue
    const int sel  = bn / splitN;
    float* Y       = (sel == 0) ? Y0 : (sel == 1) ? Y1 : Y2;
    const int nb   = bn - sel * splitN;
    #pragma unroll
    for (int i = 0; i < 2; i++) {
        #pragma unroll
        for (int j = 0; j < 4; j++) {
            int row  = bm + wm * 32 + i * 16 + g;
            int colg = bn + wn * 32 + j * 8 + 2 * tg;
            int coll = nb + wn * 32 + j * 8 + 2 * tg;
            float b0 = bias ? bias[colg]     : 0.0f;
            float b1 = bias ? bias[colg + 1] : 0.0f;
            float2 v0 = make_float2(acc[i][j][0] + b0, acc[i][j][1] + b1);
            float2 v1 = make_float2(acc[i][j][2] + b0, acc[i][j][3] + b1);
            *reinterpret_cast<float2*>(&Y[(size_t)row * Ystr + coll])       = v0;
            *reinterpret_cast<float2*>(&Y[(size_t)(row + 8) * Ystr + coll]) = v1;
        }
    }
}

// ---------------------------------------------------------------------------
// Sliding-window GQA attention (flash-style), 4 distinct kv heads. (unchanged)
// ---------------------------------------------------------------------------
__global__ void __launch_bounds__(256, 2)
attn_window(const float* __restrict__ q, const float* __restrict__ k,
            const float* __restrict__ v, float* __restrict__ out)
{
    __shared__ float Qs[32][Ddim];
    __shared__ float Ks[Ddim][33];
    __shared__ float Vs[32][Ddim];

    const int tid  = threadIdx.x;
    const int warp = tid >> 5;
    const int lane = tid & 31;

    const int bh  = blockIdx.y;
    const int b   = bh / HKVdim;
    const int kvh = bh % HKVdim;
    const int q0  = blockIdx.x * 32;

    const float* qptr = q + ((size_t)b * Sdim + q0) * KVdim + kvh * Ddim;

    #pragma unroll
    for (int e = 0; e < 16; e++) {
        int lin = e * 256 + tid;
        int r = lin >> 7, d = lin & 127;
        Qs[r][d] = qptr[(size_t)r * KVdim + d];
    }

    float m[4], l[4], O[4][4];
    #pragma unroll
    for (int r = 0; r < 4; r++) {
        m[r] = -1e30f; l[r] = 0.0f;
        #pragma unroll
        for (int c = 0; c < 4; c++) O[r][c] = 0.0f;
    }

    int ktlo = q0 - (WIN - 1);
    if (ktlo < 0) ktlo = 0;
    ktlo = (ktlo / 32) * 32;

    for (int k0 = ktlo; k0 <= q0; k0 += 32) {
        const float* kptr = k + ((size_t)b * Sdim + k0) * KVdim + kvh * Ddim;
        const float* vptr = v + ((size_t)b * Sdim + k0) * KVdim + kvh * Ddim;
        __syncthreads();
        #pragma unroll
        for (int e = 0; e < 16; e++) {
            int lin = e * 256 + tid;
            int j = lin >> 7, d = lin & 127;
            Ks[d][j] = kptr[(size_t)j * KVdim + d];
            Vs[j][d] = vptr[(size_t)j * KVdim + d];
        }
        __syncthreads();

        #pragma unroll
        for (int r = 0; r < 4; r++) {
            const int row = warp * 4 + r;
            const int i   = q0 + row;
            const int jg  = k0 + lane;

            float s = 0.0f;
            #pragma unroll
            for (int d = 0; d < Ddim; d++)
                s = fmaf(Qs[row][d], Ks[d][lane], s);

            const bool valid = (jg <= i) && (jg > i - WIN);
            s = valid ? s : -1e30f;

            float mt = s;
            #pragma unroll
            for (int off = 16; off; off >>= 1)
                mt = fmaxf(mt, __shfl_xor_sync(0xffffffffu, mt, off));
            const float mnew  = fmaxf(m[r], mt);
            const float p     = valid ? __expf(s - mnew) : 0.0f;
            const float alpha = __expf(m[r] - mnew);
            m[r] = mnew;

            float rs = p;
            #pragma unroll
            for (int off = 16; off; off >>= 1)
                rs += __shfl_xor_sync(0xffffffffu, rs, off);
            l[r] = l[r] * alpha + rs;

            #pragma unroll
            for (int c = 0; c < 4; c++) O[r][c] *= alpha;
            #pragma unroll
            for (int j = 0; j < 32; j++) {
                const float pj = __shfl_sync(0xffffffffu, p, j);
                #pragma unroll
                for (int c = 0; c < 4; c++)
                    O[r][c] = fmaf(pj, Vs[j][c * 32 + lane], O[r][c]);
            }
        }
    }

    float* optr = out + ((size_t)b * Sdim + q0) * KVdim + kvh * Ddim;
    #pragma unroll
    for (int r = 0; r < 4; r++) {
        const int row = warp * 4 + r;
        const float inv = 1.0f / l[r];
        #pragma unroll
        for (int c = 0; c < 4; c++)
            optr[(size_t)row * KVdim + c * 32 + lane] = O[r][c] * inv;
    }
}

// ---------------------------------------------------------------------------
// Launch
// ---------------------------------------------------------------------------
extern "C" void kernel_launch(void* const* d_in, const int* in_sizes, int n_in,
                              void* d_out, int out_size)
{
    const float* x  = (const float*)d_in[0];
    const float* Wq = (const float*)d_in[1];   // only rows 0..511 used
    const float* Wk = (const float*)d_in[2];
    const float* Wv = (const float*)d_in[3];
    const float* Wo = (const float*)d_in[4];
    const float* bo = (const float*)d_in[5];
    float* out = (float*)d_out;

    float *qb, *kb, *vb, *ab;
    __nv_bfloat16 *xh, *xl, *wh, *wl, *fh, *fl, *aoh, *aol;
    cudaGetSymbolAddress((void**)&qb,  g_q);
    cudaGetSymbolAddress((void**)&kb,  g_k);
    cudaGetSymbolAddress((void**)&vb,  g_v);
    cudaGetSymbolAddress((void**)&ab,  g_ao);
    cudaGetSymbolAddress((void**)&xh,  g_xh);
    cudaGetSymbolAddress((void**)&xl,  g_xl);
    cudaGetSymbolAddress((void**)&wh,  g_wh);
    cudaGetSymbolAddress((void**)&wl,  g_wl);
    cudaGetSymbolAddress((void**)&fh,  g_fh);
    cudaGetSymbolAddress((void**)&fl,  g_fl);
    cudaGetSymbolAddress((void**)&aoh, g_aoh);
    cudaGetSymbolAddress((void**)&aol, g_aol);

    static bool attr_set = false;
    if (!attr_set) {
        cudaFuncSetAttribute(gemm_ps,
                             cudaFuncAttributeMaxDynamicSharedMemorySize,
                             SMEM_TOT);
        attr_set = true;
    }

    // Conversions
    cvt_split<<<(Mrows * Edim + 255) / 256, 256>>>(x, xh, xl, Mrows * Edim);
    cvt_w<<<(NQKV * Edim + 255) / 256, 256>>>(Wq, Wk, Wv, wh, wl);
    fold_cvt<<<(Edim * KVdim + 255) / 256, 256>>>(Wo, fh, fl);

    // QKV projection (N=1536 combined; outputs split at 512)
    gemm_ps<<<dim3(NQKV / BN, Mrows / BM), 256, SMEM_TOT>>>(
        xh, xl, wh, wl, qb, kb, vb, nullptr, Edim, 512, KVdim);

    // Attention
    attn_window<<<dim3(Sdim / 32, Bdim * HKVdim), 256>>>(qb, kb, vb, ab);

    // Convert attention output
    cvt_split<<<(Mrows * KVdim + 255) / 256, 256>>>(ab, aoh, aol, Mrows * KVdim);

    // Output projection (N=2048, +bias)
    gemm_ps<<<dim3(Edim / BN, Mrows / BM), 256, SMEM_TOT>>>(
        aoh, aol, fh, fl, out, out, out, bo, KVdim, 1 << 30, Edim);
}